// round 5
// baseline (speedup 1.0000x reference)
#include <cuda_runtime.h>

#define NB 256
#define NT 1024
#define NI 64
#define NH 25
#define NG 100   // 4*H
#define NO 64
#define NM (NB*NT)  // 262144 rows

// Precomputed input gates, layout [row][k][4] = (i_k, f_k, g_k, o_k): ~105 MB
static __device__ float g_gates[(size_t)NM * NG];

typedef unsigned long long ull;

__device__ __forceinline__ ull pack2(float a, float b){
    ull r; asm("mov.b64 %0,{%1,%2};" : "=l"(r) : "f"(a), "f"(b)); return r;
}
__device__ __forceinline__ float2 unpack2(ull v){
    float2 r; asm("mov.b64 {%0,%1},%2;" : "=f"(r.x), "=f"(r.y) : "l"(v)); return r;
}
__device__ __forceinline__ ull fma2(ull a, ull b, ull c){
    ull d; asm("fma.rn.f32x2 %0,%1,%2,%3;" : "=l"(d) : "l"(a), "l"(b), "l"(c)); return d;
}
__device__ __forceinline__ ull add2(ull a, ull b){
    ull d; asm("add.rn.f32x2 %0,%1,%2;" : "=l"(d) : "l"(a), "l"(b)); return d;
}
__device__ __forceinline__ float tanha(float x){
    float r; asm("tanh.approx.f32 %0,%1;" : "=f"(r) : "f"(x)); return r;
}
__device__ __forceinline__ float sig_t(float x){
    return fmaf(tanha(0.5f * x), 0.5f, 0.5f);
}
__device__ __forceinline__ unsigned smem_u32(const void* p){
    unsigned a;
    asm("{ .reg .u64 t; cvta.to.shared.u64 t, %1; cvt.u32.u64 %0, t; }"
        : "=r"(a) : "l"(p));
    return a;
}

// ---------------------------------------------------------------------------
// Kernel 1: g_gates[row][k*4+{0..3}] = (i,f,g,o)_k pre-acts.
// LDS.128 double-k inner loop: 9 LDS.128 per 40 FMA2 (was 18 LDS.64).
// xsd padded to 34 (even -> 16B aligned rows); wps transposed k-contiguous.
// ---------------------------------------------------------------------------
__global__ void __launch_bounds__(256) gates_kernel(
    const float* __restrict__ x, const float* __restrict__ W_ih,
    const float* __restrict__ b_ih, const float* __restrict__ b_hh)
{
    __shared__ ull   xsd[100][34];    // (v,v) duplicated; stride 34 -> 16B-aligned
    __shared__ ull   wps[50][32];     // [pair c][k] k-contiguous
    __shared__ float bsum[NG];

    const int tid   = threadIdx.x;          // 0..249
    const int pairc = tid % 10;
    const int rowt  = tid / 10;             // 0..24
    const int rowbase = blockIdx.x * 100;

    ull acc[4][5];
    #pragma unroll
    for (int r = 0; r < 4; r++)
        #pragma unroll
        for (int c = 0; c < 5; c++) acc[r][c] = 0ull;

    for (int pass = 0; pass < 2; pass++){
        const int ks = pass * 32;
        for (int idx = tid; idx < 100*32; idx += 250){
            int r = idx >> 5, k = idx & 31;
            int grow = rowbase + r;
            float v = (grow < NM) ? x[(size_t)grow * NI + ks + k] : 0.0f;
            xsd[r][k] = pack2(v, v);
        }
        for (int idx = tid; idx < 32*50; idx += 250){
            int k = idx / 50, c = idx % 50;
            int r0 = (c < 25) ? c      : 25 + c;
            int r1 = (c < 25) ? 25 + c : 50 + c;
            wps[c][k] = pack2(W_ih[r0 * NI + ks + k], W_ih[r1 * NI + ks + k]);
        }
        if (pass == 0)
            for (int j = tid; j < NG; j += 250) bsum[j] = b_ih[j] + b_hh[j];
        __syncthreads();

        #pragma unroll
        for (int kk = 0; kk < 16; kk++){   // 2 k's per iteration
            ulonglong2 xd[4], wv[5];
            #pragma unroll
            for (int r = 0; r < 4; r++)
                xd[r] = *reinterpret_cast<const ulonglong2*>(&xsd[rowt + 25*r][2*kk]);
            #pragma unroll
            for (int c = 0; c < 5; c++)
                wv[c] = *reinterpret_cast<const ulonglong2*>(&wps[pairc + 10*c][2*kk]);
            #pragma unroll
            for (int r = 0; r < 4; r++)
                #pragma unroll
                for (int c = 0; c < 5; c++){
                    acc[r][c] = fma2(xd[r].x, wv[c].x, acc[r][c]);
                    acc[r][c] = fma2(xd[r].y, wv[c].y, acc[r][c]);
                }
        }
        __syncthreads();
    }

    #pragma unroll
    for (int r = 0; r < 4; r++){
        int grow = rowbase + rowt + 25*r;
        if (grow >= NM) continue;
        float* gp = g_gates + (size_t)grow * NG;
        #pragma unroll
        for (int cc = 0; cc < 5; cc++){
            int c = pairc + 10*cc;
            int base, r0, r1;
            if (c < 25){ base = 4*c;          r0 = c;      r1 = 25 + c; }
            else       { base = 4*(c-25) + 2; r0 = 25 + c; r1 = 50 + c; }
            float2 v = unpack2(acc[r][cc]);
            v.x += bsum[r0];
            v.y += bsum[r1];
            *reinterpret_cast<float2*>(gp + base) = v;
        }
    }
}

// ---------------------------------------------------------------------------
// Kernel 2: barrier-free warp-private LSTM scan + fused FC (R3 structure)
// with a cp.async smem ring for the gx stream:
//   16 slots x 16B per lane, prefetch distance 12 (one commit_group/step).
// Each lane prefetches and consumes ITS OWN slot -> no cross-thread sync.
// Slot for t+12 was last read at step t-4 -> no read/async-write hazard.
// ---------------------------------------------------------------------------
#define RD   16   // ring slots
#define RPD  12   // prefetch distance (pending groups)

__global__ void __launch_bounds__(64, 1) lstm_kernel(
    const float* __restrict__ W_hh, const float* __restrict__ W_fc,
    const float* __restrict__ b_fc, float* __restrict__ out)
{
    __shared__ ull ring[2][RD][32][2];   // [warp][slot][lane][16B]

    const int lane = threadIdx.x & 31;
    const int wrp  = threadIdx.x >> 5;
    const int b    = blockIdx.x * 2 + wrp;
    const int k    = (lane < NH) ? lane : NH - 1;   // lanes 25..31 clone k=24
    const int o0   = 2 * lane;

    const float* gx = g_gates + (size_t)b * NT * NG + 4 * k;
    float*       ob = out     + (size_t)b * NT * NO + o0;

    ull w_if[NH], w_go[NH], wf[NH];
    #pragma unroll
    for (int kk = 0; kk < NH; kk++){
        w_if[kk] = pack2(__ldg(W_hh + (     k) * NH + kk), __ldg(W_hh + (NH  + k) * NH + kk));
        w_go[kk] = pack2(__ldg(W_hh + (2*NH+k) * NH + kk), __ldg(W_hh + (3*NH+k) * NH + kk));
        wf[kk]   = pack2(__ldg(W_fc + o0 * NH + kk),       __ldg(W_fc + (o0+1) * NH + kk));
    }
    const ull bfc = pack2(__ldg(b_fc + o0), __ldg(b_fc + o0 + 1));

    const unsigned rbase = smem_u32(&ring[wrp][0][lane][0]);
    #define SLOT_ADDR(s) (rbase + (unsigned)(s) * (32u * 16u))

    // prologue: prefetch steps 0..RPD-1, one group each
    #pragma unroll
    for (int d = 0; d < RPD; d++){
        asm volatile("cp.async.ca.shared.global [%0], [%1], 16;"
                     :: "r"(SLOT_ADDR(d)), "l"(gx + (size_t)d * NG) : "memory");
        asm volatile("cp.async.commit_group;" ::: "memory");
    }

    float h = 0.0f, c = 0.0f;

    for (int tb = 0; tb < NT; tb += 4){
        #pragma unroll
        for (int u = 0; u < 4; u++){
            const int t = tb + u;
            // oldest pending group (step t) must be complete
            asm volatile("cp.async.wait_group 11;" ::: "memory");
            float4 pv = *reinterpret_cast<const float4*>(
                            &ring[wrp][t & (RD-1)][lane][0]);

            // refill: step t+RPD into its slot; empty group when out of range
            {
                unsigned pred = (t + RPD < NT) ? 1u : 0u;
                asm volatile(
                    "{ .reg .pred q; setp.ne.u32 q, %0, 0;"
                    "  @q cp.async.ca.shared.global [%1], [%2], 16; }"
                    :: "r"(pred), "r"(SLOT_ADDR((t + RPD) & (RD-1))),
                       "l"(gx + (size_t)(t + RPD) * NG) : "memory");
                asm volatile("cp.async.commit_group;" ::: "memory");
            }

            ull a_if0 = pack2(pv.x, pv.y), a_if1 = 0ull;
            ull a_go0 = pack2(pv.z, pv.w), a_go1 = 0ull;
            ull a_fc0 = bfc,               a_fc1 = 0ull;

            #pragma unroll
            for (int kk = 0; kk < NH; kk++){
                float hv = __shfl_sync(0xffffffffu, h, kk);   // h_{t-1}[kk]
                ull hd = pack2(hv, hv);
                if (kk & 1){
                    a_if1 = fma2(hd, w_if[kk], a_if1);
                    a_go1 = fma2(hd, w_go[kk], a_go1);
                    a_fc1 = fma2(hd, wf[kk],   a_fc1);
                } else {
                    a_if0 = fma2(hd, w_if[kk], a_if0);
                    a_go0 = fma2(hd, w_go[kk], a_go0);
                    a_fc0 = fma2(hd, wf[kk],   a_fc0);
                }
            }
            // FC output for h_{t-1} -> out row t-1 (off the critical path)
            if (t > 0)
                *reinterpret_cast<float2*>(ob + (size_t)(t - 1) * NO) =
                    unpack2(add2(a_fc0, a_fc1));

            float2 gif = unpack2(add2(a_if0, a_if1));
            float2 ggo = unpack2(add2(a_go0, a_go1));
            float iv = sig_t(gif.x);
            float fv = sig_t(gif.y);
            float gv = tanha(ggo.x);
            float ov = sig_t(ggo.y);
            c = fv * c + iv * gv;
            h = ov * tanha(c);
        }
    }
    // final FC for h_{T-1}
    {
        ull a0 = bfc, a1 = 0ull;
        #pragma unroll
        for (int kk = 0; kk < NH; kk++){
            float hv = __shfl_sync(0xffffffffu, h, kk);
            ull hd = pack2(hv, hv);
            if (kk & 1) a1 = fma2(hd, wf[kk], a1);
            else        a0 = fma2(hd, wf[kk], a0);
        }
        *reinterpret_cast<float2*>(ob + (size_t)(NT - 1) * NO) = unpack2(add2(a0, a1));
    }
    #undef SLOT_ADDR
}

extern "C" void kernel_launch(void* const* d_in, const int* in_sizes, int n_in,
                              void* d_out, int out_size)
{
    (void)in_sizes; (void)n_in; (void)out_size;
    const float* x    = (const float*)d_in[0];
    const float* W_ih = (const float*)d_in[1];
    const float* W_hh = (const float*)d_in[2];
    const float* b_ih = (const float*)d_in[3];
    const float* b_hh = (const float*)d_in[4];
    const float* W_fc = (const float*)d_in[5];
    const float* b_fc = (const float*)d_in[6];
    float* out = (float*)d_out;

    gates_kernel<<<(NM + 99) / 100, 250>>>(x, W_ih, b_ih, b_hh);
    lstm_kernel<<<NB / 2, 64>>>(W_hh, W_fc, b_fc, out);
}

// round 6
// speedup vs baseline: 1.8669x; 1.8669x over previous
#include <cuda_runtime.h>

#define NB 256
#define NT 1024
#define NI 64
#define NH 25
#define NG 100   // 4*H
#define NO 64
#define NM (NB*NT)  // 262144 rows

// Precomputed input gates, layout [row][k][4] = (i_k, f_k, g_k, o_k): ~105 MB
static __device__ float g_gates[(size_t)NM * NG];

typedef unsigned long long ull;

__device__ __forceinline__ ull pack2(float a, float b){
    ull r; asm("mov.b64 %0,{%1,%2};" : "=l"(r) : "f"(a), "f"(b)); return r;
}
__device__ __forceinline__ float2 unpack2(ull v){
    float2 r; asm("mov.b64 {%0,%1},%2;" : "=f"(r.x), "=f"(r.y) : "l"(v)); return r;
}
__device__ __forceinline__ ull fma2(ull a, ull b, ull c){
    ull d; asm("fma.rn.f32x2 %0,%1,%2,%3;" : "=l"(d) : "l"(a), "l"(b), "l"(c)); return d;
}
__device__ __forceinline__ ull add2(ull a, ull b){
    ull d; asm("add.rn.f32x2 %0,%1,%2;" : "=l"(d) : "l"(a), "l"(b)); return d;
}
__device__ __forceinline__ float tanha(float x){
    float r; asm("tanh.approx.f32 %0,%1;" : "=f"(r) : "f"(x)); return r;
}
__device__ __forceinline__ float sig_t(float x){
    return fmaf(tanha(0.5f * x), 0.5f, 0.5f);
}
__device__ __forceinline__ unsigned smem_u32(const void* p){
    unsigned a;
    asm("{ .reg .u64 t; cvta.to.shared.u64 t, %1; cvt.u32.u64 %0, t; }"
        : "=r"(a) : "l"(p));
    return a;
}

// ---------------------------------------------------------------------------
// Kernel 1: g_gates[row][k*4+{0..3}] = (i,f,g,o)_k pre-acts.
// R4 conflict-free wps layout (k-major, stride 50 -> banks spread).
// xd loads vectorized: xsd stride 34 (even) -> 16B-aligned LDS.128 broadcast.
// Inner loop per 2 k's: 4 LDS.128 (xd) + 10 LDS.64 (wv) + 40 FMA2.
// ---------------------------------------------------------------------------
__global__ void __launch_bounds__(256) gates_kernel(
    const float* __restrict__ x, const float* __restrict__ W_ih,
    const float* __restrict__ b_ih, const float* __restrict__ b_hh)
{
    __shared__ ull   xsd[100][34];    // (v,v) duplicated; even stride -> 16B align
    __shared__ ull   wps[32][50];     // [k][pair c] -- conflict-free (R4 layout)
    __shared__ float bsum[NG];

    const int tid   = threadIdx.x;          // 0..249
    const int pairc = tid % 10;
    const int rowt  = tid / 10;             // 0..24
    const int rowbase = blockIdx.x * 100;

    ull acc[4][5];
    #pragma unroll
    for (int r = 0; r < 4; r++)
        #pragma unroll
        for (int c = 0; c < 5; c++) acc[r][c] = 0ull;

    for (int pass = 0; pass < 2; pass++){
        const int ks = pass * 32;
        for (int idx = tid; idx < 100*32; idx += 250){
            int r = idx >> 5, k = idx & 31;
            int grow = rowbase + r;
            float v = (grow < NM) ? x[(size_t)grow * NI + ks + k] : 0.0f;
            xsd[r][k] = pack2(v, v);
        }
        for (int idx = tid; idx < 32*50; idx += 250){
            int k = idx / 50, c = idx % 50;
            int r0 = (c < 25) ? c      : 25 + c;
            int r1 = (c < 25) ? 25 + c : 50 + c;
            wps[k][c] = pack2(W_ih[r0 * NI + ks + k], W_ih[r1 * NI + ks + k]);
        }
        if (pass == 0)
            for (int j = tid; j < NG; j += 250) bsum[j] = b_ih[j] + b_hh[j];
        __syncthreads();

        #pragma unroll
        for (int kk = 0; kk < 16; kk++){   // 2 k's per iteration
            ulonglong2 xd[4];
            ull wv0[5], wv1[5];
            #pragma unroll
            for (int r = 0; r < 4; r++)
                xd[r] = *reinterpret_cast<const ulonglong2*>(&xsd[rowt + 25*r][2*kk]);
            #pragma unroll
            for (int c = 0; c < 5; c++){
                wv0[c] = wps[2*kk    ][pairc + 10*c];
                wv1[c] = wps[2*kk + 1][pairc + 10*c];
            }
            #pragma unroll
            for (int r = 0; r < 4; r++)
                #pragma unroll
                for (int c = 0; c < 5; c++){
                    acc[r][c] = fma2(xd[r].x, wv0[c], acc[r][c]);
                    acc[r][c] = fma2(xd[r].y, wv1[c], acc[r][c]);
                }
        }
        __syncthreads();
    }

    #pragma unroll
    for (int r = 0; r < 4; r++){
        int grow = rowbase + rowt + 25*r;
        if (grow >= NM) continue;
        float* gp = g_gates + (size_t)grow * NG;
        #pragma unroll
        for (int cc = 0; cc < 5; cc++){
            int c = pairc + 10*cc;
            int base, r0, r1;
            if (c < 25){ base = 4*c;          r0 = c;      r1 = 25 + c; }
            else       { base = 4*(c-25) + 2; r0 = 25 + c; r1 = 50 + c; }
            float2 v = unpack2(acc[r][cc]);
            v.x += bsum[r0];
            v.y += bsum[r1];
            *reinterpret_cast<float2*>(gp + base) = v;
        }
    }
}

// ---------------------------------------------------------------------------
// Kernel 2: warp-private LSTM scan + fused FC, cp.async gx ring (R5), with
// the SHFL h-broadcast replaced by a warp-private smem hd[] array:
//   lane k stores (h,h) once per step (STS.64); all lanes read hd[kk] via
//   LDS.64 broadcast. Per kk: 1 LDS + 3 FMA2 (was 1 SHFL + 2 MOV + 3 FMA2).
//   2 __syncwarp per step for write->read / read->write ordering.
// ---------------------------------------------------------------------------
#define RD   16   // ring slots
#define RPD  12   // prefetch distance (pending groups)

__global__ void __launch_bounds__(64, 1) lstm_kernel(
    const float* __restrict__ W_hh, const float* __restrict__ W_fc,
    const float* __restrict__ b_fc, float* __restrict__ out)
{
    __shared__ ull ring[2][RD][32][2];   // [warp][slot][lane][16B]
    __shared__ ull hdm[2][NH + 1];       // duplicated h per warp

    const int lane = threadIdx.x & 31;
    const int wrp  = threadIdx.x >> 5;
    const int b    = blockIdx.x * 2 + wrp;
    const int k    = (lane < NH) ? lane : NH - 1;   // lanes 25..31 clone k=24
    const int o0   = 2 * lane;

    const float* gx = g_gates + (size_t)b * NT * NG + 4 * k;
    float*       ob = out     + (size_t)b * NT * NO + o0;

    ull w_if[NH], w_go[NH], wf[NH];
    #pragma unroll
    for (int kk = 0; kk < NH; kk++){
        w_if[kk] = pack2(__ldg(W_hh + (     k) * NH + kk), __ldg(W_hh + (NH  + k) * NH + kk));
        w_go[kk] = pack2(__ldg(W_hh + (2*NH+k) * NH + kk), __ldg(W_hh + (3*NH+k) * NH + kk));
        wf[kk]   = pack2(__ldg(W_fc + o0 * NH + kk),       __ldg(W_fc + (o0+1) * NH + kk));
    }
    const ull bfc = pack2(__ldg(b_fc + o0), __ldg(b_fc + o0 + 1));

    const unsigned rbase = smem_u32(&ring[wrp][0][lane][0]);
    #define SLOT_ADDR(s) (rbase + (unsigned)(s) * (32u * 16u))

    // prologue: prefetch steps 0..RPD-1, one group each
    #pragma unroll
    for (int d = 0; d < RPD; d++){
        asm volatile("cp.async.ca.shared.global [%0], [%1], 16;"
                     :: "r"(SLOT_ADDR(d)), "l"(gx + (size_t)d * NG) : "memory");
        asm volatile("cp.async.commit_group;" ::: "memory");
    }

    float h = 0.0f, c = 0.0f;
    if (lane < NH) hdm[wrp][lane] = 0ull;   // h0 = 0 (duplicated)
    __syncwarp();

    for (int tb = 0; tb < NT; tb += 4){
        #pragma unroll
        for (int u = 0; u < 4; u++){
            const int t = tb + u;
            asm volatile("cp.async.wait_group 11;" ::: "memory");
            float4 pv = *reinterpret_cast<const float4*>(
                            &ring[wrp][t & (RD-1)][lane][0]);

            {   // refill: step t+RPD into its slot; empty group when done
                unsigned pred = (t + RPD < NT) ? 1u : 0u;
                asm volatile(
                    "{ .reg .pred q; setp.ne.u32 q, %0, 0;"
                    "  @q cp.async.ca.shared.global [%1], [%2], 16; }"
                    :: "r"(pred), "r"(SLOT_ADDR((t + RPD) & (RD-1))),
                       "l"(gx + (size_t)(t + RPD) * NG) : "memory");
                asm volatile("cp.async.commit_group;" ::: "memory");
            }

            ull a_if0 = pack2(pv.x, pv.y), a_if1 = 0ull;
            ull a_go0 = pack2(pv.z, pv.w), a_go1 = 0ull;
            ull a_fc0 = bfc,               a_fc1 = 0ull;

            #pragma unroll
            for (int kk = 0; kk < NH; kk++){
                ull hd = hdm[wrp][kk];           // LDS.64 broadcast
                if (kk & 1){
                    a_if1 = fma2(hd, w_if[kk], a_if1);
                    a_go1 = fma2(hd, w_go[kk], a_go1);
                    a_fc1 = fma2(hd, wf[kk],   a_fc1);
                } else {
                    a_if0 = fma2(hd, w_if[kk], a_if0);
                    a_go0 = fma2(hd, w_go[kk], a_go0);
                    a_fc0 = fma2(hd, wf[kk],   a_fc0);
                }
            }
            // FC output for h_{t-1} -> out row t-1 (off the critical path)
            if (t > 0)
                *reinterpret_cast<float2*>(ob + (size_t)(t - 1) * NO) =
                    unpack2(add2(a_fc0, a_fc1));

            float2 gif = unpack2(add2(a_if0, a_if1));
            float2 ggo = unpack2(add2(a_go0, a_go1));
            float iv = sig_t(gif.x);
            float fv = sig_t(gif.y);
            float gv = tanha(ggo.x);
            float ov = sig_t(ggo.y);
            c = fv * c + iv * gv;
            h = ov * tanha(c);

            __syncwarp();                        // all reads of hd done
            if (lane < NH) hdm[wrp][lane] = pack2(h, h);
            __syncwarp();                        // new hd visible
        }
    }
    // final FC for h_{T-1}
    {
        ull a0 = bfc, a1 = 0ull;
        #pragma unroll
        for (int kk = 0; kk < NH; kk++){
            ull hd = hdm[wrp][kk];
            if (kk & 1) a1 = fma2(hd, wf[kk], a1);
            else        a0 = fma2(hd, wf[kk], a0);
        }
        *reinterpret_cast<float2*>(ob + (size_t)(NT - 1) * NO) = unpack2(add2(a0, a1));
    }
    #undef SLOT_ADDR
}

extern "C" void kernel_launch(void* const* d_in, const int* in_sizes, int n_in,
                              void* d_out, int out_size)
{
    (void)in_sizes; (void)n_in; (void)out_size;
    const float* x    = (const float*)d_in[0];
    const float* W_ih = (const float*)d_in[1];
    const float* W_hh = (const float*)d_in[2];
    const float* b_ih = (const float*)d_in[3];
    const float* b_hh = (const float*)d_in[4];
    const float* W_fc = (const float*)d_in[5];
    const float* b_fc = (const float*)d_in[6];
    float* out = (float*)d_out;

    gates_kernel<<<(NM + 99) / 100, 250>>>(x, W_ih, b_ih, b_hh);
    lstm_kernel<<<NB / 2, 64>>>(W_hh, W_fc, b_fc, out);
}

// round 7
// speedup vs baseline: 2.1003x; 1.1250x over previous
#include <cuda_runtime.h>

#define NB 256
#define NT 1024
#define NI 64
#define NH 25
#define NG 100   // 4*H
#define NO 64
#define NM (NB*NT)  // 262144 rows
#define GROWS 150   // gates tile rows

// Precomputed input gates, layout [row][k][4] = (i_k, f_k, g_k, o_k): ~105 MB
static __device__ float g_gates[(size_t)NM * NG];

typedef unsigned long long ull;

__device__ __forceinline__ ull pack2(float a, float b){
    ull r; asm("mov.b64 %0,{%1,%2};" : "=l"(r) : "f"(a), "f"(b)); return r;
}
__device__ __forceinline__ float2 unpack2(ull v){
    float2 r; asm("mov.b64 {%0,%1},%2;" : "=f"(r.x), "=f"(r.y) : "l"(v)); return r;
}
__device__ __forceinline__ ull fma2(ull a, ull b, ull c){
    ull d; asm("fma.rn.f32x2 %0,%1,%2,%3;" : "=l"(d) : "l"(a), "l"(b), "l"(c)); return d;
}
__device__ __forceinline__ ull add2(ull a, ull b){
    ull d; asm("add.rn.f32x2 %0,%1,%2;" : "=l"(d) : "l"(a), "l"(b)); return d;
}
__device__ __forceinline__ float tanha(float x){
    float r; asm("tanh.approx.f32 %0,%1;" : "=f"(r) : "f"(x)); return r;
}
__device__ __forceinline__ float sig_t(float x){
    return fmaf(tanha(0.5f * x), 0.5f, 0.5f);
}
__device__ __forceinline__ unsigned smem_u32(const void* p){
    unsigned a;
    asm("{ .reg .u64 t; cvta.to.shared.u64 t, %1; cvt.u32.u64 %0, t; }"
        : "=r"(a) : "l"(p));
    return a;
}

// ---------------------------------------------------------------------------
// Kernel 1: g_gates[row][k*4+{0..3}] = (i,f,g,o)_k pre-acts.
// Crossbar-lean version: x stored UNduplicated (float, stride 34), loaded as
// float2 (2 k's per 8B, all bytes useful), duplicated to (v,v) in registers.
// Tile 150 rows x 100 cols, 250 threads, 6 rows x 5 pairs per thread.
// Per 2 k's: 6 LDS.64 (x) + 10 LDS.64 (w) = 32 crossbar-cyc per 60 FMA2.
// ---------------------------------------------------------------------------
__global__ void __launch_bounds__(256) gates_kernel(
    const float* __restrict__ x, const float* __restrict__ W_ih,
    const float* __restrict__ b_ih, const float* __restrict__ b_hh)
{
    __shared__ float xs[GROWS][34];   // even stride -> float2 loads 8B-aligned
    __shared__ ull   wps[32][50];     // [k][pair c] conflict-free layout
    __shared__ float bsum[NG];

    const int tid   = threadIdx.x;          // 0..249
    const int pairc = tid % 10;
    const int rowt  = tid / 10;             // 0..24
    const int rowbase = blockIdx.x * GROWS;

    ull acc[6][5];
    #pragma unroll
    for (int r = 0; r < 6; r++)
        #pragma unroll
        for (int c = 0; c < 5; c++) acc[r][c] = 0ull;

    for (int pass = 0; pass < 2; pass++){
        const int ks = pass * 32;
        for (int idx = tid; idx < GROWS*32; idx += 250){
            int r = idx >> 5, k = idx & 31;
            int grow = rowbase + r;
            xs[r][k] = (grow < NM) ? x[(size_t)grow * NI + ks + k] : 0.0f;
        }
        for (int idx = tid; idx < 32*50; idx += 250){
            int k = idx / 50, c = idx % 50;
            int r0 = (c < 25) ? c      : 25 + c;
            int r1 = (c < 25) ? 25 + c : 50 + c;
            wps[k][c] = pack2(W_ih[r0 * NI + ks + k], W_ih[r1 * NI + ks + k]);
        }
        if (pass == 0)
            for (int j = tid; j < NG; j += 250) bsum[j] = b_ih[j] + b_hh[j];
        __syncthreads();

        #pragma unroll
        for (int kk = 0; kk < 16; kk++){   // 2 k's per iteration
            float2 xv[6];
            ull    wv0[5], wv1[5];
            #pragma unroll
            for (int r = 0; r < 6; r++)
                xv[r] = *reinterpret_cast<const float2*>(&xs[rowt + 25*r][2*kk]);
            #pragma unroll
            for (int c = 0; c < 5; c++){
                wv0[c] = wps[2*kk    ][pairc + 10*c];
                wv1[c] = wps[2*kk + 1][pairc + 10*c];
            }
            ull xd0[6], xd1[6];
            #pragma unroll
            for (int r = 0; r < 6; r++){
                xd0[r] = pack2(xv[r].x, xv[r].x);
                xd1[r] = pack2(xv[r].y, xv[r].y);
            }
            #pragma unroll
            for (int r = 0; r < 6; r++)
                #pragma unroll
                for (int c = 0; c < 5; c++){
                    acc[r][c] = fma2(xd0[r], wv0[c], acc[r][c]);
                    acc[r][c] = fma2(xd1[r], wv1[c], acc[r][c]);
                }
        }
        __syncthreads();
    }

    #pragma unroll
    for (int r = 0; r < 6; r++){
        int grow = rowbase + rowt + 25*r;
        if (grow >= NM) continue;
        float* gp = g_gates + (size_t)grow * NG;
        #pragma unroll
        for (int cc = 0; cc < 5; cc++){
            int c = pairc + 10*cc;
            int base, r0, r1;
            if (c < 25){ base = 4*c;          r0 = c;      r1 = 25 + c; }
            else       { base = 4*(c-25) + 2; r0 = 25 + c; r1 = 50 + c; }
            float2 v = unpack2(acc[r][cc]);
            v.x += bsum[r0];
            v.y += bsum[r1];
            *reinterpret_cast<float2*>(gp + base) = v;
        }
    }
}

// ---------------------------------------------------------------------------
// Kernel 2: warp-private LSTM scan + fused FC (R5 shfl structure) with
// 4-way accumulator trees (FMA2 reduction depth 13 -> 7 on the serial path).
// cp.async smem ring for the gx stream: 16 slots x 16B/lane, distance 12.
// ---------------------------------------------------------------------------
#define RD   16   // ring slots
#define RPD  12   // prefetch distance (pending groups)

__global__ void __launch_bounds__(64, 1) lstm_kernel(
    const float* __restrict__ W_hh, const float* __restrict__ W_fc,
    const float* __restrict__ b_fc, float* __restrict__ out)
{
    __shared__ ull ring[2][RD][32][2];   // [warp][slot][lane][16B]

    const int lane = threadIdx.x & 31;
    const int wrp  = threadIdx.x >> 5;
    const int b    = blockIdx.x * 2 + wrp;
    const int k    = (lane < NH) ? lane : NH - 1;   // lanes 25..31 clone k=24
    const int o0   = 2 * lane;

    const float* gx = g_gates + (size_t)b * NT * NG + 4 * k;
    float*       ob = out     + (size_t)b * NT * NO + o0;

    ull w_if[NH], w_go[NH], wf[NH];
    #pragma unroll
    for (int kk = 0; kk < NH; kk++){
        w_if[kk] = pack2(__ldg(W_hh + (     k) * NH + kk), __ldg(W_hh + (NH  + k) * NH + kk));
        w_go[kk] = pack2(__ldg(W_hh + (2*NH+k) * NH + kk), __ldg(W_hh + (3*NH+k) * NH + kk));
        wf[kk]   = pack2(__ldg(W_fc + o0 * NH + kk),       __ldg(W_fc + (o0+1) * NH + kk));
    }
    const ull bfc = pack2(__ldg(b_fc + o0), __ldg(b_fc + o0 + 1));

    const unsigned rbase = smem_u32(&ring[wrp][0][lane][0]);
    #define SLOT_ADDR(s) (rbase + (unsigned)(s) * (32u * 16u))

    // prologue: prefetch steps 0..RPD-1, one group each
    #pragma unroll
    for (int d = 0; d < RPD; d++){
        asm volatile("cp.async.ca.shared.global [%0], [%1], 16;"
                     :: "r"(SLOT_ADDR(d)), "l"(gx + (size_t)d * NG) : "memory");
        asm volatile("cp.async.commit_group;" ::: "memory");
    }

    float h = 0.0f, c = 0.0f;

    for (int tb = 0; tb < NT; tb += 4){
        #pragma unroll
        for (int u = 0; u < 4; u++){
            const int t = tb + u;
            asm volatile("cp.async.wait_group 11;" ::: "memory");
            float4 pv = *reinterpret_cast<const float4*>(
                            &ring[wrp][t & (RD-1)][lane][0]);

            {   // refill: step t+RPD into its slot; empty group when done
                unsigned pred = (t + RPD < NT) ? 1u : 0u;
                asm volatile(
                    "{ .reg .pred q; setp.ne.u32 q, %0, 0;"
                    "  @q cp.async.ca.shared.global [%1], [%2], 16; }"
                    :: "r"(pred), "r"(SLOT_ADDR((t + RPD) & (RD-1))),
                       "l"(gx + (size_t)(t + RPD) * NG) : "memory");
                asm volatile("cp.async.commit_group;" ::: "memory");
            }

            // 4-way accumulator trees (reduction depth 7)
            ull aif[4], ago[4], afc[2];
            aif[0] = pack2(pv.x, pv.y); aif[1] = 0ull; aif[2] = 0ull; aif[3] = 0ull;
            ago[0] = pack2(pv.z, pv.w); ago[1] = 0ull; ago[2] = 0ull; ago[3] = 0ull;
            afc[0] = bfc;               afc[1] = 0ull;

            #pragma unroll
            for (int kk = 0; kk < NH; kk++){
                float hv = __shfl_sync(0xffffffffu, h, kk);   // h_{t-1}[kk]
                ull hd = pack2(hv, hv);
                aif[kk & 3] = fma2(hd, w_if[kk], aif[kk & 3]);
                ago[kk & 3] = fma2(hd, w_go[kk], ago[kk & 3]);
                afc[kk & 1] = fma2(hd, wf[kk],   afc[kk & 1]);
            }
            // FC output for h_{t-1} -> out row t-1 (off the critical path)
            if (t > 0)
                *reinterpret_cast<float2*>(ob + (size_t)(t - 1) * NO) =
                    unpack2(add2(afc[0], afc[1]));

            float2 gif = unpack2(add2(add2(aif[0], aif[1]), add2(aif[2], aif[3])));
            float2 ggo = unpack2(add2(add2(ago[0], ago[1]), add2(ago[2], ago[3])));
            float iv = sig_t(gif.x);
            float fv = sig_t(gif.y);
            float gv = tanha(ggo.x);
            float ov = sig_t(ggo.y);
            c = fv * c + iv * gv;
            h = ov * tanha(c);
        }
    }
    // final FC for h_{T-1}
    {
        ull a0 = bfc, a1 = 0ull;
        #pragma unroll
        for (int kk = 0; kk < NH; kk++){
            float hv = __shfl_sync(0xffffffffu, h, kk);
            ull hd = pack2(hv, hv);
            if (kk & 1) a1 = fma2(hd, wf[kk], a1);
            else        a0 = fma2(hd, wf[kk], a0);
        }
        *reinterpret_cast<float2*>(ob + (size_t)(NT - 1) * NO) = unpack2(add2(a0, a1));
    }
    #undef SLOT_ADDR
}

extern "C" void kernel_launch(void* const* d_in, const int* in_sizes, int n_in,
                              void* d_out, int out_size)
{
    (void)in_sizes; (void)n_in; (void)out_size;
    const float* x    = (const float*)d_in[0];
    const float* W_ih = (const float*)d_in[1];
    const float* W_hh = (const float*)d_in[2];
    const float* b_ih = (const float*)d_in[3];
    const float* b_hh = (const float*)d_in[4];
    const float* W_fc = (const float*)d_in[5];
    const float* b_fc = (const float*)d_in[6];
    float* out = (float*)d_out;

    gates_kernel<<<(NM + GROWS - 1) / GROWS, 250>>>(x, W_ih, b_ih, b_hh);
    lstm_kernel<<<NB / 2, 64>>>(W_hh, W_fc, b_fc, out);
}